// round 7
// baseline (speedup 1.0000x reference)
#include <cuda_runtime.h>
#include <math_constants.h>

// ---------------------------------------------------------------------------
// TSFuzzyLayer: per-edge fuzzy attention + global softmax over edge_sg_ID set
// Softmax note: attention values are analytically bounded (|attn| <= ~3), so
// max-subtraction is unnecessary in fp32; plain sum-of-exp (fixed combine
// order => deterministic).
// ---------------------------------------------------------------------------

#define MAXPART 8192

__device__ float g_psum[MAXPART];
__device__ float g_invsum;
__device__ int   g_count = 0;      // last-block-done counter (self-resetting)

// ---- fast acos in degrees (A&S 4.4.45, max err 6.7e-5 rad = 0.0038 deg) ----
__device__ __forceinline__ float acos_deg(float c)
{
    float a = fabsf(c);
    float p = fmaf(a, -0.0187293f, 0.0742610f);
    p = fmaf(a, p, -0.2121144f);
    p = fmaf(a, p, 1.5707288f);
    float r = sqrtf(1.0f - a) * p;
    float ac = (c < 0.0f) ? (CUDART_PI_F - r) : r;
    return ac * 57.29577951308232f;
}

// ---- phase 1: raw features -> (x1, x2) ------------------------------------
__device__ __forceinline__ void edge_x1x2(
    float4 fs, float4 fd, float& x1, float& x2)
{
    float d0 = fd.x - fs.x;
    float d1 = fd.y - fs.y;
    float v0 = fd.z - fs.z;
    float v1 = fd.w - fs.w;
    x1 = sqrtf(fmaf(d0, d0, d1 * d1));
    float vn = sqrtf(fmaf(v0, v0, v1 * v1));
    float dotv = fmaf(d0, v0, d1 * v1);
    float c = __fdividef(dotv, fmaf(x1, vn, 1e-8f));
    c = fminf(fmaxf(c, -1.0f + 1e-6f), 1.0f - 1e-6f);
    x2 = acos_deg(c);
}

// ---- phase 2: (x1, x2) -> attention ---------------------------------------
// Gaussian membership factorization: for means {0,2,4}, sigma 0.75:
//   m1[0] = exp(-a*x1^2),  a = 1/1.125
//   m1[1] = m1[0] * T,     T = exp(4a*(x1-1))
//   m1[2] = m1[1] * T * exp(-8a)        (exp(-64/9) = 8.15988e-4)
// For means {0,90,180}, sigma 30 (b = 1/1800, 180b = 0.1, 8100b = 4.5):
//   m2[1] = m2[0] * U,     U = exp(0.1*x2 - 4.5)
//   m2[2] = m2[1] * U * exp(-9)         (1.2340980e-4)
__device__ __forceinline__ float edge_rules(
    float x1, float x2,
    const float* __restrict__ sM0, const float* __restrict__ sM1,
    const float* __restrict__ sB)
{
    float m1[3], m2[3];
    float E0 = __expf(-0.88888889f * x1 * x1);
    float T  = __expf(fmaf(3.55555556f, x1, -3.55555556f));
    m1[0] = E0;
    m1[1] = E0 * T;
    m1[2] = m1[1] * T * 8.15988e-4f;

    float F0 = __expf(-5.5555556e-4f * x2 * x2);
    float U  = __expf(fmaf(0.1f, x2, -4.5f));
    m2[0] = F0;
    m2[1] = F0 * U;
    m2[2] = m2[1] * U * 1.2340980e-4f;

    float num = 0.0f, den = 0.0f;
    #pragma unroll
    for (int i = 0; i < 3; ++i) {
        #pragma unroll
        for (int j = 0; j < 3; ++j) {
            int r = i * 3 + j;
            float tm = fminf(m1[i], m2[j]);
            float cons = fmaf(x1, sM0[r], fmaf(x2, sM1[r], sB[r]));
            num = fmaf(tm, cons, num);
            den += tm;
        }
    }
    return __fdividef(num, den);
}

// -------------------------- pass 1: per-edge attention ----------------------
// 2 edges/thread; low register footprint -> 6 CTAs/SM for deep L1tex queue.
__global__ void __launch_bounds__(256, 6) edge_attention_kernel(
    const float* __restrict__ feat,
    const int*   __restrict__ src,
    const int*   __restrict__ dst,
    const float* __restrict__ mat,
    const float* __restrict__ bias,
    float* __restrict__ out,
    int n_edges)
{
    __shared__ float sM0[9], sM1[9], sB[9];
    int t = threadIdx.x;
    if (t < 9)       sM0[t]      = mat[t];
    else if (t < 18) sM1[t - 9]  = mat[t];
    else if (t < 27) sB[t - 18]  = bias[t - 18];
    __syncthreads();

    int n2 = n_edges >> 1;
    int k = blockIdx.x * blockDim.x + t;

    if (k < n2) {
        int2 sa = reinterpret_cast<const int2*>(src)[k];
        int2 da = reinterpret_cast<const int2*>(dst)[k];
        const float4* f4 = reinterpret_cast<const float4*>(feat);

        // issue all 4 gathers up front
        float4 fs0 = __ldg(f4 + sa.x);
        float4 fd0 = __ldg(f4 + da.x);
        float4 fs1 = __ldg(f4 + sa.y);
        float4 fd1 = __ldg(f4 + da.y);

        float x1a, x2a, x1b, x2b;
        edge_x1x2(fs0, fd0, x1a, x2a);
        edge_x1x2(fs1, fd1, x1b, x2b);

        float2 r;
        r.x = edge_rules(x1a, x2a, sM0, sM1, sB);
        r.y = edge_rules(x1b, x2b, sM0, sM1, sB);
        reinterpret_cast<float2*>(out)[k] = r;
    }

    // tail (n_edges odd)
    int tail = n_edges - (n2 << 1);
    if (blockIdx.x == 0 && t < tail) {
        int e = (n2 << 1) + t;
        const float4* f4 = reinterpret_cast<const float4*>(feat);
        float4 fs = __ldg(f4 + src[e]);
        float4 fd = __ldg(f4 + dst[e]);
        float x1, x2;
        edge_x1x2(fs, fd, x1, x2);
        out[e] = edge_rules(x1, x2, sM0, sM1, sB);
    }
}

// ------------- pass 2: sum-of-exp reduction + last-block combine ------------
__global__ void __launch_bounds__(256) softmax_reduce_kernel(
    const float* __restrict__ out,
    const int*   __restrict__ idx,
    int n_sg)
{
    int n4 = n_sg >> 2;
    float s = 0.0f;

    const int4* i4p = reinterpret_cast<const int4*>(idx);
    for (int k = blockIdx.x * blockDim.x + threadIdx.x; k < n4;
         k += gridDim.x * blockDim.x) {
        int4 ia = i4p[k];
        float v0 = __ldg(out + ia.x);
        float v1 = __ldg(out + ia.y);
        float v2 = __ldg(out + ia.z);
        float v3 = __ldg(out + ia.w);
        s += __expf(v0) + __expf(v1) + __expf(v2) + __expf(v3);
    }

    int tail = n_sg - (n4 << 2);
    if (blockIdx.x == 0 && threadIdx.x < tail) {
        s += __expf(__ldg(out + idx[(n4 << 2) + threadIdx.x]));
    }

    // intra-block sum
    #pragma unroll
    for (int o = 16; o > 0; o >>= 1)
        s += __shfl_xor_sync(0xFFFFFFFFu, s, o);
    __shared__ float ss[8];
    __shared__ int s_last;
    int wid = threadIdx.x >> 5, lid = threadIdx.x & 31;
    if (lid == 0) ss[wid] = s;
    __syncthreads();
    if (wid == 0) {
        s = (lid < 8) ? ss[lid] : 0.0f;
        #pragma unroll
        for (int o = 4; o > 0; o >>= 1)
            s += __shfl_xor_sync(0xFFFFFFFFu, s, o);
        if (lid == 0) g_psum[blockIdx.x] = s;
    }
    __threadfence();
    if (threadIdx.x == 0) {
        int v = atomicAdd(&g_count, 1);
        s_last = (v == (int)gridDim.x - 1);
    }
    __syncthreads();
    if (!s_last) return;

    // last block: combine partials (fixed order -> deterministic)
    float acc = 0.0f;
    for (int i = threadIdx.x; i < (int)gridDim.x; i += blockDim.x)
        acc += g_psum[i];
    #pragma unroll
    for (int o = 16; o > 0; o >>= 1)
        acc += __shfl_xor_sync(0xFFFFFFFFu, acc, o);
    if (lid == 0) ss[wid] = acc;
    __syncthreads();
    if (wid == 0) {
        acc = (lid < 8) ? ss[lid] : 0.0f;
        #pragma unroll
        for (int o = 4; o > 0; o >>= 1)
            acc += __shfl_xor_sync(0xFFFFFFFFu, acc, o);
        if (lid == 0) {
            g_invsum = 1.0f / acc;
            g_count = 0;               // reset for next graph replay
        }
    }
}

// ----------------------- pass 3: normalize in place -------------------------
__global__ void __launch_bounds__(256) softmax_write_kernel(
    float* __restrict__ out,
    const int* __restrict__ idx,
    int n_sg)
{
    float invS = g_invsum;

    int n4 = n_sg >> 2;
    int k = blockIdx.x * blockDim.x + threadIdx.x;

    if (k < n4) {
        int4 ia = reinterpret_cast<const int4*>(idx)[k];
        float v0 = out[ia.x];
        float v1 = out[ia.y];
        float v2 = out[ia.z];
        float v3 = out[ia.w];
        out[ia.x] = __expf(v0) * invS;
        out[ia.y] = __expf(v1) * invS;
        out[ia.z] = __expf(v2) * invS;
        out[ia.w] = __expf(v3) * invS;
    }

    int tail = n_sg - (n4 << 2);
    if (blockIdx.x == 0 && threadIdx.x < tail) {
        int j = idx[(n4 << 2) + threadIdx.x];
        out[j] = __expf(out[j]) * invS;
    }
}

// ---------------------------------------------------------------------------
extern "C" void kernel_launch(void* const* d_in, const int* in_sizes, int n_in,
                              void* d_out, int out_size)
{
    const float* feat = (const float*)d_in[0];
    const int*   src  = (const int*)  d_in[1];
    const int*   dst  = (const int*)  d_in[2];
    const int*   sgid = (const int*)  d_in[3];
    const float* mat  = (const float*)d_in[4];
    const float* bias = (const float*)d_in[5];
    float* out = (float*)d_out;

    int n_edges = in_sizes[1];
    int n_sg    = in_sizes[3];

    int n2e = n_edges >> 1;
    int blocks1 = (n2e + 255) / 256;
    if (blocks1 < 1) blocks1 = 1;
    edge_attention_kernel<<<blocks1, 256>>>(feat, src, dst, mat, bias, out, n_edges);

    int n4s = n_sg >> 2;
    int blocksR = (n4s + 255) / 256;
    if (blocksR < 1) blocksR = 1;
    if (blocksR > MAXPART) blocksR = MAXPART;
    softmax_reduce_kernel<<<blocksR, 256>>>(out, sgid, n_sg);

    int blocksW = (n4s + 255) / 256;
    if (blocksW < 1) blocksW = 1;
    softmax_write_kernel<<<blocksW, 256>>>(out, sgid, n_sg);
}

// round 8
// speedup vs baseline: 1.0520x; 1.0520x over previous
#include <cuda_runtime.h>
#include <math_constants.h>

// ---------------------------------------------------------------------------
// TSFuzzyLayer: per-edge fuzzy attention + global softmax over edge_sg_ID set
// Softmax note: attention values are analytically bounded (|attn| <= ~3), so
// max-subtraction is unnecessary in fp32; plain sum-of-exp (fixed combine
// order => deterministic).
// ---------------------------------------------------------------------------

#define MAXPART 8192

__device__ float g_psum[MAXPART];
__device__ float g_invsum;
__device__ int   g_count = 0;      // last-block-done counter (self-resetting)

// ---- fast acos in degrees (A&S 4.4.45, max err 6.7e-5 rad = 0.0038 deg) ----
__device__ __forceinline__ float acos_deg(float c)
{
    float a = fabsf(c);
    float p = fmaf(a, -0.0187293f, 0.0742610f);
    p = fmaf(a, p, -0.2121144f);
    p = fmaf(a, p, 1.5707288f);
    float r = sqrtf(1.0f - a) * p;
    float ac = (c < 0.0f) ? (CUDART_PI_F - r) : r;
    return ac * 57.29577951308232f;
}

// ---- phase 1: raw features -> (x1, x2) ------------------------------------
__device__ __forceinline__ void edge_x1x2(
    float4 fs, float4 fd, float& x1, float& x2)
{
    float d0 = fd.x - fs.x;
    float d1 = fd.y - fs.y;
    float v0 = fd.z - fs.z;
    float v1 = fd.w - fs.w;
    x1 = sqrtf(fmaf(d0, d0, d1 * d1));
    float vn = sqrtf(fmaf(v0, v0, v1 * v1));
    float dotv = fmaf(d0, v0, d1 * v1);
    float c = __fdividef(dotv, fmaf(x1, vn, 1e-8f));
    c = fminf(fmaxf(c, -1.0f + 1e-6f), 1.0f - 1e-6f);
    x2 = acos_deg(c);
}

// ---- phase 2: (x1, x2) -> attention ---------------------------------------
// Gaussian membership factorization (4 exps instead of 6):
//   m1[0] = exp(-a*x1^2), a=8/9;  T = exp(4a(x1-1));  m1[1]=m1[0]T;
//   m1[2] = m1[1]*T*exp(-8a)  (exp(-64/9)=8.15988e-4)
//   m2[0] = exp(-b*x2^2), b=1/1800; U = exp(0.1*x2-4.5); m2[1]=m2[0]U;
//   m2[2] = m2[1]*U*exp(-9)   (1.2340980e-4)
__device__ __forceinline__ float edge_rules(
    float x1, float x2,
    const float* __restrict__ sM0, const float* __restrict__ sM1,
    const float* __restrict__ sB)
{
    float m1[3], m2[3];
    float E0 = __expf(-0.88888889f * x1 * x1);
    float T  = __expf(fmaf(3.55555556f, x1, -3.55555556f));
    m1[0] = E0;
    m1[1] = E0 * T;
    m1[2] = m1[1] * T * 8.15988e-4f;

    float F0 = __expf(-5.5555556e-4f * x2 * x2);
    float U  = __expf(fmaf(0.1f, x2, -4.5f));
    m2[0] = F0;
    m2[1] = F0 * U;
    m2[2] = m2[1] * U * 1.2340980e-4f;

    float num = 0.0f, den = 0.0f;
    #pragma unroll
    for (int i = 0; i < 3; ++i) {
        #pragma unroll
        for (int j = 0; j < 3; ++j) {
            int r = i * 3 + j;
            float tm = fminf(m1[i], m2[j]);
            float cons = fmaf(x1, sM0[r], fmaf(x2, sM1[r], sB[r]));
            num = fmaf(tm, cons, num);
            den += tm;
        }
    }
    return __fdividef(num, den);
}

// -------------------------- pass 1: per-edge attention ----------------------
// 4 edges/thread in two 2-edge batches (R6 config: best measured 33.4us,
// 48 regs, 5 CTAs/SM).
__global__ void __launch_bounds__(256, 5) edge_attention_kernel(
    const float* __restrict__ feat,
    const int*   __restrict__ src,
    const int*   __restrict__ dst,
    const float* __restrict__ mat,
    const float* __restrict__ bias,
    float* __restrict__ out,
    int n_edges)
{
    __shared__ float sM0[9], sM1[9], sB[9];
    int t = threadIdx.x;
    if (t < 9)       sM0[t]      = mat[t];
    else if (t < 18) sM1[t - 9]  = mat[t];
    else if (t < 27) sB[t - 18]  = bias[t - 18];
    __syncthreads();

    int n4 = n_edges >> 2;
    int k = blockIdx.x * blockDim.x + t;

    if (k < n4) {
        int4 sa = reinterpret_cast<const int4*>(src)[k];
        int4 da = reinterpret_cast<const int4*>(dst)[k];
        const float4* f4 = reinterpret_cast<const float4*>(feat);

        float x1a, x2a, x1b, x2b, x1c, x2c, x1d, x2d;

        // batch 1: edges 0,1
        {
            float4 fs0 = __ldg(f4 + sa.x);
            float4 fd0 = __ldg(f4 + da.x);
            float4 fs1 = __ldg(f4 + sa.y);
            float4 fd1 = __ldg(f4 + da.y);
            edge_x1x2(fs0, fd0, x1a, x2a);
            edge_x1x2(fs1, fd1, x1b, x2b);
        }
        // batch 2: edges 2,3
        {
            float4 fs2 = __ldg(f4 + sa.z);
            float4 fd2 = __ldg(f4 + da.z);
            float4 fs3 = __ldg(f4 + sa.w);
            float4 fd3 = __ldg(f4 + da.w);
            edge_x1x2(fs2, fd2, x1c, x2c);
            edge_x1x2(fs3, fd3, x1d, x2d);
        }

        float4 r;
        r.x = edge_rules(x1a, x2a, sM0, sM1, sB);
        r.y = edge_rules(x1b, x2b, sM0, sM1, sB);
        r.z = edge_rules(x1c, x2c, sM0, sM1, sB);
        r.w = edge_rules(x1d, x2d, sM0, sM1, sB);
        reinterpret_cast<float4*>(out)[k] = r;
    }

    int tail = n_edges - (n4 << 2);
    if (blockIdx.x == 0 && t < tail) {
        int e = (n4 << 2) + t;
        const float4* f4 = reinterpret_cast<const float4*>(feat);
        float4 fs = __ldg(f4 + src[e]);
        float4 fd = __ldg(f4 + dst[e]);
        float x1, x2;
        edge_x1x2(fs, fd, x1, x2);
        out[e] = edge_rules(x1, x2, sM0, sM1, sB);
    }
}

// ------------- pass 2: sum-of-exp reduction + last-block combine ------------
__global__ void __launch_bounds__(256) softmax_reduce_kernel(
    const float* __restrict__ out,
    const int*   __restrict__ idx,
    int n_sg)
{
    int n4 = n_sg >> 2;
    float s = 0.0f;

    const int4* i4p = reinterpret_cast<const int4*>(idx);
    for (int k = blockIdx.x * blockDim.x + threadIdx.x; k < n4;
         k += gridDim.x * blockDim.x) {
        int4 ia = i4p[k];
        float v0 = __ldg(out + ia.x);
        float v1 = __ldg(out + ia.y);
        float v2 = __ldg(out + ia.z);
        float v3 = __ldg(out + ia.w);
        s += __expf(v0) + __expf(v1) + __expf(v2) + __expf(v3);
    }

    int tail = n_sg - (n4 << 2);
    if (blockIdx.x == 0 && threadIdx.x < tail) {
        s += __expf(__ldg(out + idx[(n4 << 2) + threadIdx.x]));
    }

    // intra-block sum
    #pragma unroll
    for (int o = 16; o > 0; o >>= 1)
        s += __shfl_xor_sync(0xFFFFFFFFu, s, o);
    __shared__ float ss[8];
    __shared__ int s_last;
    int wid = threadIdx.x >> 5, lid = threadIdx.x & 31;
    if (lid == 0) ss[wid] = s;
    __syncthreads();
    if (wid == 0) {
        s = (lid < 8) ? ss[lid] : 0.0f;
        #pragma unroll
        for (int o = 4; o > 0; o >>= 1)
            s += __shfl_xor_sync(0xFFFFFFFFu, s, o);
        if (lid == 0) g_psum[blockIdx.x] = s;
    }
    __threadfence();
    if (threadIdx.x == 0) {
        int v = atomicAdd(&g_count, 1);
        s_last = (v == (int)gridDim.x - 1);
    }
    __syncthreads();
    if (!s_last) return;

    // last block: combine partials (fixed order -> deterministic)
    float acc = 0.0f;
    for (int i = threadIdx.x; i < (int)gridDim.x; i += blockDim.x)
        acc += g_psum[i];
    #pragma unroll
    for (int o = 16; o > 0; o >>= 1)
        acc += __shfl_xor_sync(0xFFFFFFFFu, acc, o);
    if (lid == 0) ss[wid] = acc;
    __syncthreads();
    if (wid == 0) {
        acc = (lid < 8) ? ss[lid] : 0.0f;
        #pragma unroll
        for (int o = 4; o > 0; o >>= 1)
            acc += __shfl_xor_sync(0xFFFFFFFFu, acc, o);
        if (lid == 0) {
            g_invsum = 1.0f / acc;
            g_count = 0;               // reset for next graph replay
        }
    }
}

// ----------------------- pass 3: normalize in place -------------------------
__global__ void __launch_bounds__(256) softmax_write_kernel(
    float* __restrict__ out,
    const int* __restrict__ idx,
    int n_sg)
{
    float invS = g_invsum;

    int n4 = n_sg >> 2;
    int k = blockIdx.x * blockDim.x + threadIdx.x;

    if (k < n4) {
        int4 ia = reinterpret_cast<const int4*>(idx)[k];
        float v0 = out[ia.x];
        float v1 = out[ia.y];
        float v2 = out[ia.z];
        float v3 = out[ia.w];
        out[ia.x] = __expf(v0) * invS;
        out[ia.y] = __expf(v1) * invS;
        out[ia.z] = __expf(v2) * invS;
        out[ia.w] = __expf(v3) * invS;
    }

    int tail = n_sg - (n4 << 2);
    if (blockIdx.x == 0 && threadIdx.x < tail) {
        int j = idx[(n4 << 2) + threadIdx.x];
        out[j] = __expf(out[j]) * invS;
    }
}

// ---------------------------------------------------------------------------
extern "C" void kernel_launch(void* const* d_in, const int* in_sizes, int n_in,
                              void* d_out, int out_size)
{
    const float* feat = (const float*)d_in[0];
    const int*   src  = (const int*)  d_in[1];
    const int*   dst  = (const int*)  d_in[2];
    const int*   sgid = (const int*)  d_in[3];
    const float* mat  = (const float*)d_in[4];
    const float* bias = (const float*)d_in[5];
    float* out = (float*)d_out;

    int n_edges = in_sizes[1];
    int n_sg    = in_sizes[3];

    int n4e = n_edges >> 2;
    int blocks1 = (n4e + 255) / 256;
    if (blocks1 < 1) blocks1 = 1;
    edge_attention_kernel<<<blocks1, 256>>>(feat, src, dst, mat, bias, out, n_edges);

    int n4s = n_sg >> 2;
    int blocksR = (n4s + 255) / 256;
    if (blocksR < 1) blocksR = 1;
    if (blocksR > MAXPART) blocksR = MAXPART;
    softmax_reduce_kernel<<<blocksR, 256>>>(out, sgid, n_sg);

    int blocksW = (n4s + 255) / 256;
    if (blocksW < 1) blocksW = 1;
    softmax_write_kernel<<<blocksW, 256>>>(out, sgid, n_sg);
}